// round 16
// baseline (speedup 1.0000x reference)
#include <cuda_runtime.h>

// EfficientPWL, intercept form: out = x * a[i1] + b[i1]
// a[i1] = slopes[c, i1], b[i1] = cumbias[c, i2] - cp[i2]*slopes[c, i1],
// i2 = max(i1-1,0), uniform breakpoints linspace(-1,1,33), dt = 1/16.
//
// B=32, C=128, T=8192. FINAL configuration (measured best, R11):
//  - one block per (b,c) row        (1/2-row and 4-row both slower)
//  - plain LDG.128/STG.128 only     (__ldcs: -15us; v8 256-bit: -1.1us via occ)
//  - 256 threads, 32 regs, 8 CTA/SM (__launch_bounds__(256,8))
//  - warp-scan prologue, ONE __syncthreads (-0.7us vs serial chain)
//  - front-batched MLP=8 loads, then compute+store
// 36.9us kernel = 7.27 TB/s app-level = 91% of 8 TB/s HBM spec.

#define CCH     128
#define TLEN    8192
#define NCP     33
#define NSL     34
#define THREADS 256
#define VPT     8       // float4 per thread (full row / 256 threads)

__global__ void __launch_bounds__(THREADS, 8)
efficient_pwl_kernel(const float* __restrict__ x,
                     const float* __restrict__ slopes,
                     const float* __restrict__ biases,
                     float* __restrict__ out) {
    __shared__ float2 s_tab[NSL];   // (a, b) per bucket index i1

    const int row = blockIdx.x;          // b*C + c
    const int c   = row & (CCH - 1);
    const int tid = threadIdx.x;

    if (tid < 32) {
        const unsigned FULL = 0xffffffffu;
        const float dt   = 0.0625f;
        const float bias = biases[c];

        // lane j holds slopes[c, j+1] * dt  (covers slope[1..32])
        float s = slopes[c * NSL + tid + 1] * dt;

        // inclusive warp scan: lane j -> dt * sum_{i=1..j+1} slope[i]
        #pragma unroll
        for (int d = 1; d < 32; d <<= 1) {
            float t = __shfl_up_sync(FULL, s, d);
            if (tid >= d) s += t;
        }
        // cumb[k]: k=0 -> bias; k>=1 -> scan lane (k-1) + bias.

        // ---- tab[t] for t = tid (0..31), shuffles warp-converged ----
        {
            const int   t    = tid;
            const int   i2   = max(t - 1, 0);            // 0..30
            const int   src  = (i2 > 0) ? (i2 - 1) : 0;
            float cumb = __shfl_sync(FULL, s, src);
            cumb = (i2 > 0) ? (cumb + bias) : bias;
            const float a  = slopes[c * NSL + t];
            const float cp = -1.0f + 0.0625f * (float)i2;
            s_tab[t] = make_float2(a, fmaf(-cp, a, cumb));
        }

        // ---- tab[32], tab[33]: shuffles unconditional, writes predicated ----
        const float cumb31 = __shfl_sync(FULL, s, 30) + bias;  // cumb[31]
        const float cumb32 = __shfl_sync(FULL, s, 31) + bias;  // cumb[32]
        if (tid < 2) {
            const int   t    = 32 + tid;          // 32 or 33
            const int   i2   = t - 1;             // 31 or 32
            const float cumb = (tid == 0) ? cumb31 : cumb32;
            const float a    = slopes[c * NSL + t];
            const float cp   = -1.0f + 0.0625f * (float)i2;
            s_tab[t] = make_float2(a, fmaf(-cp, a, cumb));
        }
    }
    __syncthreads();

    const float4* __restrict__ xin = (const float4*)(x + (size_t)row * TLEN);
    float4* __restrict__ o         = (float4*)(out + (size_t)row * TLEN);

    // Front-batched loads (MLP = 8), then compute + store.
    float4 v[VPT];
    #pragma unroll
    for (int i = 0; i < VPT; i++)
        v[i] = xin[tid + i * THREADS];

    #pragma unroll
    for (int i = 0; i < VPT; i++) {
        float4 r;
        #pragma unroll
        for (int j = 0; j < 4; j++) {
            const float xv = (&v[i].x)[j];
            int i1 = __float2int_rd(fmaf(xv, 16.0f, 16.0f)) + 1;
            i1 = max(0, min(NCP, i1));
            const float2 ab = s_tab[i1];
            (&r.x)[j] = fmaf(xv, ab.x, ab.y);
        }
        o[tid + i * THREADS] = r;
    }
}

extern "C" void kernel_launch(void* const* d_in, const int* in_sizes, int n_in,
                              void* d_out, int out_size) {
    const float* x      = (const float*)d_in[0];
    const float* slopes = (const float*)d_in[1];
    const float* biases = (const float*)d_in[2];
    float* out          = (float*)d_out;

    efficient_pwl_kernel<<<4096, THREADS>>>(x, slopes, biases, out);
}

// round 17
// speedup vs baseline: 1.0170x; 1.0170x over previous
#include <cuda_runtime.h>

// EfficientPWL, intercept form: out = x * a[i1] + b[i1]
// a[i1] = slopes[c, i1], b[i1] = cumbias[c, i2] - cp[i2]*slopes[c, i1],
// i2 = max(i1-1,0), uniform breakpoints linspace(-1,1,33), dt = 1/16.
//
// B=32, C=128, T=8192. R17 experiment: 512-thread blocks, 1 row per block,
// VPT=4. Same total resident threads/SM (4 CTA x 512 = 8 CTA x 256); halves
// the per-byte shadow of the single-warp table prologue. Everything else
// identical to the validated R11 configuration.

#define CCH     128
#define TLEN    8192
#define NCP     33
#define NSL     34
#define THREADS 512
#define VPT     4       // float4 per thread (2048 float4 / 512 threads)

__global__ void __launch_bounds__(THREADS, 4)
efficient_pwl_kernel(const float* __restrict__ x,
                     const float* __restrict__ slopes,
                     const float* __restrict__ biases,
                     float* __restrict__ out) {
    __shared__ float2 s_tab[NSL];   // (a, b) per bucket index i1

    const int row = blockIdx.x;          // b*C + c
    const int c   = row & (CCH - 1);
    const int tid = threadIdx.x;

    if (tid < 32) {
        const unsigned FULL = 0xffffffffu;
        const float dt   = 0.0625f;
        const float bias = biases[c];

        // lane j holds slopes[c, j+1] * dt  (covers slope[1..32])
        float s = slopes[c * NSL + tid + 1] * dt;

        // inclusive warp scan: lane j -> dt * sum_{i=1..j+1} slope[i]
        #pragma unroll
        for (int d = 1; d < 32; d <<= 1) {
            float t = __shfl_up_sync(FULL, s, d);
            if (tid >= d) s += t;
        }
        // cumb[k]: k=0 -> bias; k>=1 -> scan lane (k-1) + bias.

        // ---- tab[t] for t = tid (0..31), shuffles warp-converged ----
        {
            const int   t    = tid;
            const int   i2   = max(t - 1, 0);            // 0..30
            const int   src  = (i2 > 0) ? (i2 - 1) : 0;
            float cumb = __shfl_sync(FULL, s, src);
            cumb = (i2 > 0) ? (cumb + bias) : bias;
            const float a  = slopes[c * NSL + t];
            const float cp = -1.0f + 0.0625f * (float)i2;
            s_tab[t] = make_float2(a, fmaf(-cp, a, cumb));
        }

        // ---- tab[32], tab[33]: shuffles unconditional, writes predicated ----
        const float cumb31 = __shfl_sync(FULL, s, 30) + bias;  // cumb[31]
        const float cumb32 = __shfl_sync(FULL, s, 31) + bias;  // cumb[32]
        if (tid < 2) {
            const int   t    = 32 + tid;          // 32 or 33
            const int   i2   = t - 1;             // 31 or 32
            const float cumb = (tid == 0) ? cumb31 : cumb32;
            const float a    = slopes[c * NSL + t];
            const float cp   = -1.0f + 0.0625f * (float)i2;
            s_tab[t] = make_float2(a, fmaf(-cp, a, cumb));
        }
    }
    __syncthreads();

    const float4* __restrict__ xin = (const float4*)(x + (size_t)row * TLEN);
    float4* __restrict__ o         = (float4*)(out + (size_t)row * TLEN);

    // Front-batched loads (MLP = 4 per thread, 2048 lines per block), then
    // compute + store.
    float4 v[VPT];
    #pragma unroll
    for (int i = 0; i < VPT; i++)
        v[i] = xin[tid + i * THREADS];

    #pragma unroll
    for (int i = 0; i < VPT; i++) {
        float4 r;
        #pragma unroll
        for (int j = 0; j < 4; j++) {
            const float xv = (&v[i].x)[j];
            int i1 = __float2int_rd(fmaf(xv, 16.0f, 16.0f)) + 1;
            i1 = max(0, min(NCP, i1));
            const float2 ab = s_tab[i1];
            (&r.x)[j] = fmaf(xv, ab.x, ab.y);
        }
        o[tid + i * THREADS] = r;
    }
}

extern "C" void kernel_launch(void* const* d_in, const int* in_sizes, int n_in,
                              void* d_out, int out_size) {
    const float* x      = (const float*)d_in[0];
    const float* slopes = (const float*)d_in[1];
    const float* biases = (const float*)d_in[2];
    float* out          = (float*)d_out;

    efficient_pwl_kernel<<<4096, THREADS>>>(x, slopes, biases, out);
}